// round 6
// baseline (speedup 1.0000x reference)
#include <cuda_runtime.h>
#include <math_constants.h>

#define BETA_MIN 0.1f
#define BETA_MAX 20.0f

#define DDIM 128
#define BM 32
#define BN 64
#define NTHREADS 256
#define MAX_M 16384

// Scratch (static __device__ globals are the allowed scratch mechanism)
__device__ float g_y2[MAX_M];                      // ||y_m||^2
__device__ float g_yT[(size_t)DDIM * MAX_M];       // Y transposed [d][m]

// ---------------------------------------------------------------------------
// Precompute 1: y2[m] = sum_d Y[m][d]^2   (one warp per row)
// ---------------------------------------------------------------------------
__global__ void gmm_y2_kernel(const float* __restrict__ Y, int M) {
    int row = blockIdx.x * 8 + threadIdx.y;
    if (row >= M) return;
    int l = threadIdx.x;
    float4 v = *reinterpret_cast<const float4*>(Y + (size_t)row * DDIM + l * 4);
    float s = v.x * v.x + v.y * v.y + v.z * v.z + v.w * v.w;
#pragma unroll
    for (int off = 16; off > 0; off >>= 1)
        s += __shfl_xor_sync(0xffffffffu, s, off);
    if (l == 0) g_y2[row] = s;
}

// ---------------------------------------------------------------------------
// Precompute 2: g_yT[d][m] = Y[m][d]  (smem tiled transpose, 32x32 tiles)
// ---------------------------------------------------------------------------
__global__ void gmm_transpose_kernel(const float* __restrict__ Y, int M) {
    __shared__ float tile[32][33];
    int m0 = blockIdx.x * 32;
    int d0 = blockIdx.y * 32;
    int tx = threadIdx.x, ty = threadIdx.y;
#pragma unroll
    for (int j = ty; j < 32; j += 8)
        tile[j][tx] = Y[(size_t)(m0 + j) * DDIM + d0 + tx];
    __syncthreads();
#pragma unroll
    for (int j = ty; j < 32; j += 8)
        g_yT[(size_t)(d0 + j) * M + m0 + tx] = tile[tx][j];
}

// ---------------------------------------------------------------------------
// Main fused kernel: online-softmax attention over all M keys.
//   score[r][c] = a_r * <x_r, y_c> + b_r * ||y_c||^2   (constant term dropped)
//   out[r][:]   = (softmax_row @ Y - x_r) * inv_var_r
// ---------------------------------------------------------------------------
__global__ __launch_bounds__(NTHREADS, 1)
void gmm_main_kernel(const float* __restrict__ X, const float* __restrict__ T,
                     const float* __restrict__ Y, float* __restrict__ out, int M) {
    extern __shared__ float sm[];
    float* sh_xsT = sm;                 // [128][32]  a_r * x_r, transposed
    float* sh_yT  = sm + 4096;          // [128][64]  Y tile transposed (GEMM1)
    float* sh_yn  = sm + 12288;         // [64][128]  Y tile row-major (GEMM2)
    float* sh_p   = sm + 20480;         // [64][36]   P transposed [c][r], padded
    float* sh_y2  = sm + 22784;         // [64]

    __shared__ float sh_b[BM], sh_inv[BM], sh_a[BM];
    __shared__ float sh_m[BM], sh_l[BM], sh_scale[BM], sh_mnew[BM];
    __shared__ float sh_wmax[2][BM], sh_wsum[2][BM];

    const int tid  = threadIdx.x;
    const int lane = tid & 31;
    const int wid  = tid >> 5;
    const int r0   = blockIdx.x * BM;

    // Per-row VP-SDE marginals
    if (tid < BM) {
        float tv   = T[r0 + tid];
        float lm   = -0.25f * tv * tv * (BETA_MAX - BETA_MIN) - 0.5f * tv * BETA_MIN;
        float mean = expf(lm);
        float em2  = expf(2.0f * lm);
        float var  = fmaxf(1.0f - em2, 1e-12f);
        float inv  = 1.0f / var;
        sh_a[tid]   = mean * inv;
        sh_b[tid]   = -0.5f * mean * mean * inv;
        sh_inv[tid] = inv;
        sh_m[tid]   = -CUDART_INF_F;
        sh_l[tid]   = 0.0f;
    }
    __syncthreads();

    // Build xsT[d][r] = a_r * x[r][d]
    {
        int d4 = lane * 4;
#pragma unroll
        for (int it = 0; it < 4; it++) {
            int r = it * 8 + wid;
            float4 v = *reinterpret_cast<const float4*>(X + (size_t)(r0 + r) * DDIM + d4);
            float a = sh_a[r];
            sh_xsT[(d4 + 0) * BM + r] = a * v.x;
            sh_xsT[(d4 + 1) * BM + r] = a * v.y;
            sh_xsT[(d4 + 2) * BM + r] = a * v.z;
            sh_xsT[(d4 + 3) * BM + r] = a * v.w;
        }
    }

    // GEMM2 accumulators: rows 4*wid..+3, dims 4*lane..+3
    float acc[4][4];
#pragma unroll
    for (int i = 0; i < 4; i++)
#pragma unroll
        for (int j = 0; j < 4; j++) acc[i][j] = 0.f;

    const int h    = wid >> 2;          // GEMM1 column half (0/1)
    const int rblk = (wid & 3) * 8;     // GEMM1 row block (8 rows)
    const int c1   = h * 32 + lane;     // GEMM1 column within tile

    const int ntiles = M / BN;
    for (int tile = 0; tile < ntiles; tile++) {
        const int c0 = tile * BN;
        __syncthreads();  // previous iteration's consumers done with smem tiles

        // Load yT tile [128][64] from pre-transposed global (coalesced)
        {
            int cg    = (tid & 15) * 4;
            int dbase = tid >> 4;  // 0..15
#pragma unroll
            for (int it = 0; it < 8; it++) {
                int d = it * 16 + dbase;
                float4 v = *reinterpret_cast<const float4*>(&g_yT[(size_t)d * M + c0 + cg]);
                *reinterpret_cast<float4*>(&sh_yT[d * BN + cg]) = v;
            }
        }
        // Load yn tile [64][128] (coalesced)
        {
            int d4 = (tid & 31) * 4;
            int cb = tid >> 5;  // 0..7
#pragma unroll
            for (int it = 0; it < 8; it++) {
                int c = it * 8 + cb;
                float4 v = *reinterpret_cast<const float4*>(Y + (size_t)(c0 + c) * DDIM + d4);
                *reinterpret_cast<float4*>(&sh_yn[c * DDIM + d4]) = v;
            }
        }
        if (tid < BN) sh_y2[tid] = g_y2[c0 + tid];
        __syncthreads();

        // ---- GEMM1: s[r][c1] = sum_d xsT[d][r] * yT[d][c1]
        float s[8];
#pragma unroll
        for (int i = 0; i < 8; i++) s[i] = 0.f;
#pragma unroll 4
        for (int d = 0; d < DDIM; d++) {
            float  yv = sh_yT[d * BN + c1];
            float4 xa = *reinterpret_cast<const float4*>(&sh_xsT[d * BM + rblk]);
            float4 xb = *reinterpret_cast<const float4*>(&sh_xsT[d * BM + rblk + 4]);
            s[0] += xa.x * yv; s[1] += xa.y * yv; s[2] += xa.z * yv; s[3] += xa.w * yv;
            s[4] += xb.x * yv; s[5] += xb.y * yv; s[6] += xb.z * yv; s[7] += xb.w * yv;
        }
        {
            float y2c = sh_y2[c1];
#pragma unroll
            for (int i = 0; i < 8; i++) s[i] += sh_b[rblk + i] * y2c;
        }

        // ---- row max across this warp's 32 columns
        float mx[8];
#pragma unroll
        for (int i = 0; i < 8; i++) mx[i] = s[i];
#pragma unroll
        for (int off = 16; off > 0; off >>= 1) {
#pragma unroll
            for (int i = 0; i < 8; i++)
                mx[i] = fmaxf(mx[i], __shfl_xor_sync(0xffffffffu, mx[i], off));
        }
        if (lane == 0) {
#pragma unroll
            for (int i = 0; i < 8; i++) sh_wmax[h][rblk + i] = mx[i];
        }
        __syncthreads();

        if (tid < BM) {
            float tm = fmaxf(sh_wmax[0][tid], sh_wmax[1][tid]);
            float mo = sh_m[tid];
            float mn = fmaxf(mo, tm);
            sh_scale[tid] = __expf(mo - mn);
            sh_mnew[tid]  = mn;
            sh_m[tid]     = mn;
        }
        __syncthreads();

        // ---- p = exp(s - m_new), write P^T to smem, row sums
        float su[8];
#pragma unroll
        for (int i = 0; i < 8; i++) {
            float p = __expf(s[i] - sh_mnew[rblk + i]);
            sh_p[c1 * 36 + rblk + i] = p;
            su[i] = p;
        }
#pragma unroll
        for (int off = 16; off > 0; off >>= 1) {
#pragma unroll
            for (int i = 0; i < 8; i++)
                su[i] += __shfl_xor_sync(0xffffffffu, su[i], off);
        }
        if (lane == 0) {
#pragma unroll
            for (int i = 0; i < 8; i++) sh_wsum[h][rblk + i] = su[i];
        }
        __syncthreads();

        if (tid < BM)
            sh_l[tid] = sh_l[tid] * sh_scale[tid] + sh_wsum[0][tid] + sh_wsum[1][tid];

        // ---- GEMM2: acc[r][d] = acc*scale + sum_c P[r][c] * yn[c][d]
        {
            float sc[4];
#pragma unroll
            for (int i = 0; i < 4; i++) sc[i] = sh_scale[4 * wid + i];
#pragma unroll
            for (int i = 0; i < 4; i++)
#pragma unroll
                for (int j = 0; j < 4; j++) acc[i][j] *= sc[i];

#pragma unroll 2
            for (int cc = 0; cc < BN; cc++) {
                float4 yv = *reinterpret_cast<const float4*>(&sh_yn[cc * DDIM + 4 * lane]);
                float4 pv = *reinterpret_cast<const float4*>(&sh_p[cc * 36 + 4 * wid]);
                acc[0][0] += pv.x * yv.x; acc[0][1] += pv.x * yv.y;
                acc[0][2] += pv.x * yv.z; acc[0][3] += pv.x * yv.w;
                acc[1][0] += pv.y * yv.x; acc[1][1] += pv.y * yv.y;
                acc[1][2] += pv.y * yv.z; acc[1][3] += pv.y * yv.w;
                acc[2][0] += pv.z * yv.x; acc[2][1] += pv.z * yv.y;
                acc[2][2] += pv.z * yv.z; acc[2][3] += pv.z * yv.w;
                acc[3][0] += pv.w * yv.x; acc[3][1] += pv.w * yv.y;
                acc[3][2] += pv.w * yv.z; acc[3][3] += pv.w * yv.w;
            }
        }
    }

    __syncthreads();  // final l_run ready

    // Epilogue: out = (acc/l - x) * inv_var
#pragma unroll
    for (int i = 0; i < 4; i++) {
        int r = 4 * wid + i;
        float inv_l = 1.0f / sh_l[r];
        float iv    = sh_inv[r];
        float4 xv = *reinterpret_cast<const float4*>(X + (size_t)(r0 + r) * DDIM + 4 * lane);
        float4 o;
        o.x = (acc[i][0] * inv_l - xv.x) * iv;
        o.y = (acc[i][1] * inv_l - xv.y) * iv;
        o.z = (acc[i][2] * inv_l - xv.z) * iv;
        o.w = (acc[i][3] * inv_l - xv.w) * iv;
        *reinterpret_cast<float4*>(out + (size_t)(r0 + r) * DDIM + 4 * lane) = o;
    }
}

// ---------------------------------------------------------------------------
extern "C" void kernel_launch(void* const* d_in, const int* in_sizes, int n_in,
                              void* d_out, int out_size) {
    (void)n_in; (void)out_size;
    const float* x = (const float*)d_in[0];
    const float* t = (const float*)d_in[1];
    const float* y = (const float*)d_in[2];
    float* out = (float*)d_out;

    int N = in_sizes[1];
    int M = in_sizes[2] / DDIM;

    const int smem_bytes = 22848 * 4;  // 91392 B
    cudaFuncSetAttribute(gmm_main_kernel,
                         cudaFuncAttributeMaxDynamicSharedMemorySize, smem_bytes);

    gmm_y2_kernel<<<(M + 7) / 8, dim3(32, 8)>>>(y, M);
    gmm_transpose_kernel<<<dim3(M / 32, DDIM / 32), dim3(32, 8)>>>(y, M);
    gmm_main_kernel<<<N / BM, NTHREADS, smem_bytes>>>(x, t, y, out, M);
}

// round 8
// speedup vs baseline: 6.1480x; 6.1480x over previous
#include <cuda_runtime.h>
#include <cuda_bf16.h>
#include <math_constants.h>
#include <cstdint>

#define BETA_MIN 0.1f
#define BETA_MAX 20.0f
#define LOG2E 1.4426950408889634f
#define DDIM 128
#define NROWS 4096
#define MKEYS 16384
#define SPLITK 4
#define BM 128
#define BN 64
#define NT 64            // key tiles per CTA (MKEYS/SPLITK/BN)
#define TILES_ALL 256

// smem byte offsets
#define XS_H 0
#define XS_L 32768
#define Y1H  65536
#define Y1L  81920
#define YTH  98304
#define YTL  114688
#define SMEM_BYTES 131072

__device__ float g_y2[MKEYS];
__device__ uint4 g_y1h[TILES_ALL * 1024];   // Y tile [key][d], bf16 hi, XOR-swizzled
__device__ uint4 g_y1l[TILES_ALL * 1024];   // lo
__device__ uint4 g_yth[TILES_ALL * 1024];   // Y^T tile [d][key], bf16 hi, XOR-swizzled
__device__ uint4 g_ytl[TILES_ALL * 1024];   // lo
__device__ float g_pO[(size_t)SPLITK * NROWS * DDIM];
__device__ float g_pm[SPLITK * NROWS];
__device__ float g_pl[SPLITK * NROWS];

// ---------------- helpers ----------------
// fast 2^v for v <= 0 (clamped at -30), FFMA/ALU pipes only
__device__ __forceinline__ float fexp2(float v) {
    v = fmaxf(v, -30.0f);
    float r = v + 12582912.0f;
    int   n = __float_as_int(r) - 0x4B400000;
    float f = v - (r - 12582912.0f);
    float p = 1.3333558146e-3f;
    p = fmaf(p, f, 9.6181291918e-3f);
    p = fmaf(p, f, 5.5504108664e-2f);
    p = fmaf(p, f, 2.4022650696e-1f);
    p = fmaf(p, f, 6.9314718056e-1f);
    p = fmaf(p, f, 1.0f);
    return __int_as_float(__float_as_int(p) + (n << 23));
}
// split (a,b) -> bf16x2 hi (low half = a) + bf16x2 lo residual
__device__ __forceinline__ void split2(float a, float b, uint32_t& h, uint32_t& l) {
    uint32_t hp, lp;
    asm("cvt.rn.bf16x2.f32 %0, %1, %2;" : "=r"(hp) : "f"(b), "f"(a));
    float ra = a - __int_as_float(hp << 16);
    float rb = b - __int_as_float(hp & 0xFFFF0000u);
    asm("cvt.rn.bf16x2.f32 %0, %1, %2;" : "=r"(lp) : "f"(rb), "f"(ra));
    h = hp; l = lp;
}
__device__ __forceinline__ void mma16816(float* c, const uint32_t* a, uint32_t b0, uint32_t b1) {
    asm volatile("mma.sync.aligned.m16n8k16.row.col.f32.bf16.bf16.f32 "
        "{%0,%1,%2,%3}, {%4,%5,%6,%7}, {%8,%9}, {%0,%1,%2,%3};"
        : "+f"(c[0]), "+f"(c[1]), "+f"(c[2]), "+f"(c[3])
        : "r"(a[0]), "r"(a[1]), "r"(a[2]), "r"(a[3]), "r"(b0), "r"(b1));
}

// ---------------- precompute: y2 ----------------
__global__ void gmm_y2_kernel(const float* __restrict__ Y, int M) {
    int row = blockIdx.x * 8 + threadIdx.y;
    if (row >= M) return;
    int l = threadIdx.x;
    float4 v = *reinterpret_cast<const float4*>(Y + (size_t)row * DDIM + l * 4);
    float s = v.x * v.x + v.y * v.y + v.z * v.z + v.w * v.w;
#pragma unroll
    for (int off = 16; off > 0; off >>= 1) s += __shfl_xor_sync(0xffffffffu, s, off);
    if (l == 0) g_y2[row] = s;
}

// ---------------- precompute: split + swizzled tile blobs ----------------
__global__ void gmm_prep_kernel(const float* __restrict__ Y) {
    int tile = blockIdx.x, t = threadIdx.x, c0 = tile * BN;
    // GEMM1 blob: [64 keys][128 d], elem (key,d) at key*256 + ((d*2) ^ ((key&7)*32))
    {
        int key = t >> 2, dq = (t & 3) * 32;
        const float* src = Y + (size_t)(c0 + key) * DDIM;
#pragma unroll
        for (int i = 0; i < 4; i++) {
            int d = dq + 8 * i;
            float4 v0 = *reinterpret_cast<const float4*>(src + d);
            float4 v1 = *reinterpret_cast<const float4*>(src + d + 4);
            uint32_t hh[4], ll[4];
            split2(v0.x, v0.y, hh[0], ll[0]); split2(v0.z, v0.w, hh[1], ll[1]);
            split2(v1.x, v1.y, hh[2], ll[2]); split2(v1.z, v1.w, hh[3], ll[3]);
            uint32_t off = (uint32_t)key * 256 + ((uint32_t)(d * 2) ^ ((key & 7) * 32));
            g_y1h[tile * 1024 + off / 16] = make_uint4(hh[0], hh[1], hh[2], hh[3]);
            g_y1l[tile * 1024 + off / 16] = make_uint4(ll[0], ll[1], ll[2], ll[3]);
        }
    }
    // GEMM2 blob: Y^T [128 d][64 keys], elem (d,key) at d*128 + ((key*2) ^ ((d&7)*16))
    {
        int dim = t >> 1, kh = (t & 1) * 32;
#pragma unroll
        for (int i = 0; i < 4; i++) {
            int k0 = kh + 8 * i;
            float pv[8];
#pragma unroll
            for (int u = 0; u < 8; u++) pv[u] = Y[(size_t)(c0 + k0 + u) * DDIM + dim];
            uint32_t hh[4], ll[4];
            split2(pv[0], pv[1], hh[0], ll[0]); split2(pv[2], pv[3], hh[1], ll[1]);
            split2(pv[4], pv[5], hh[2], ll[2]); split2(pv[6], pv[7], hh[3], ll[3]);
            uint32_t off = (uint32_t)dim * 128 + ((uint32_t)(k0 * 2) ^ ((dim & 7) * 16));
            g_yth[tile * 1024 + off / 16] = make_uint4(hh[0], hh[1], hh[2], hh[3]);
            g_ytl[tile * 1024 + off / 16] = make_uint4(ll[0], ll[1], ll[2], ll[3]);
        }
    }
}

// ---------------- main fused kernel ----------------
__global__ __launch_bounds__(256, 1)
void gmm_main_kernel(const float* __restrict__ X, const float* __restrict__ T) {
    extern __shared__ uint8_t sb[];
    __shared__ float sh_a2[BM], sh_b2[BM];
    __shared__ float sh_y2[BN];

    const int tid = threadIdx.x, lane = tid & 31, wid = tid >> 5;
    const int rb = blockIdx.x >> 2, q = blockIdx.x & 3;
    const int r0 = rb * BM;
    const int rw = wid * 16;            // warp's 16-row group
    const int rsub = lane >> 2;         // 0..7
    const uint32_t lb4 = (uint32_t)(lane & 3) * 4;
    const uint32_t swA = (uint32_t)rsub * 32;   // GEMM1 swizzle XOR
    const uint32_t swB = (uint32_t)rsub * 16;   // GEMM2 swizzle XOR

    if (tid < BM) {
        float tv = T[r0 + tid];
        float lm = -0.25f * tv * tv * (BETA_MAX - BETA_MIN) - 0.5f * tv * BETA_MIN;
        float mean = expf(lm);
        float var = fmaxf(1.0f - expf(2.0f * lm), 1e-12f);
        float iv = 1.0f / var;
        sh_a2[tid] = mean * iv * LOG2E;
        sh_b2[tid] = -0.5f * mean * mean * iv * LOG2E;
    }
    __syncthreads();

    // Build A = a2_r * x_r in smem, bf16 split, swizzled [128 rows][128 d]
    {
        int row = tid >> 1, half = tid & 1;
        float a2 = sh_a2[row];
        const float* src = X + (size_t)(r0 + row) * DDIM + half * 64;
#pragma unroll
        for (int i = 0; i < 8; i++) {
            int d = half * 64 + 8 * i;
            float4 v0 = *reinterpret_cast<const float4*>(src + 8 * i);
            float4 v1 = *reinterpret_cast<const float4*>(src + 8 * i + 4);
            uint32_t hh[4], ll[4];
            split2(a2 * v0.x, a2 * v0.y, hh[0], ll[0]);
            split2(a2 * v0.z, a2 * v0.w, hh[1], ll[1]);
            split2(a2 * v1.x, a2 * v1.y, hh[2], ll[2]);
            split2(a2 * v1.z, a2 * v1.w, hh[3], ll[3]);
            uint32_t off = (uint32_t)row * 256 + ((uint32_t)(d * 2) ^ ((row & 7) * 32));
            *reinterpret_cast<uint4*>(sb + XS_H + off) = make_uint4(hh[0], hh[1], hh[2], hh[3]);
            *reinterpret_cast<uint4*>(sb + XS_L + off) = make_uint4(ll[0], ll[1], ll[2], ll[3]);
        }
    }

    const float b2a = sh_b2[rw + rsub];
    const float b2b = sh_b2[rw + rsub + 8];

    float o[16][4];
#pragma unroll
    for (int i = 0; i < 16; i++)
#pragma unroll
        for (int j = 0; j < 4; j++) o[i][j] = 0.0f;
    float m_a = -CUDART_INF_F, m_b = -CUDART_INF_F, l_a = 0.0f, l_b = 0.0f;

    for (int kt = 0; kt < NT; kt++) {
        const int tg = q * NT + kt;
        __syncthreads();   // previous tile fully consumed
        {
            const uint4* s1 = g_y1h + tg * 1024; uint4* d1 = (uint4*)(sb + Y1H);
            const uint4* s2 = g_y1l + tg * 1024; uint4* d2 = (uint4*)(sb + Y1L);
            const uint4* s3 = g_yth + tg * 1024; uint4* d3 = (uint4*)(sb + YTH);
            const uint4* s4 = g_ytl + tg * 1024; uint4* d4 = (uint4*)(sb + YTL);
#pragma unroll
            for (int i = 0; i < 4; i++) {
                int idx = tid + 256 * i;
                d1[idx] = s1[idx]; d2[idx] = s2[idx]; d3[idx] = s3[idx]; d4[idx] = s4[idx];
            }
        }
        if (tid < BN) sh_y2[tid] = g_y2[tg * BN + tid];
        __syncthreads();

        // ---- GEMM1: S[16][64] per warp, 4-term bf16 split, K=128 ----
        float s[8][4];
#pragma unroll
        for (int i = 0; i < 8; i++)
#pragma unroll
            for (int j = 0; j < 4; j++) s[i][j] = 0.0f;

#pragma unroll 2
        for (int kc = 0; kc < 8; kc++) {
            uint32_t oA = ((uint32_t)kc * 32 + lb4) ^ swA;
            const uint8_t* arow = sb + XS_H + (rw + rsub) * 256;
            uint32_t ah[4], al[4];
            ah[0] = *(const uint32_t*)(arow + oA);
            ah[1] = *(const uint32_t*)(arow + 2048 + oA);
            ah[2] = *(const uint32_t*)(arow + oA + 16);
            ah[3] = *(const uint32_t*)(arow + 2048 + oA + 16);
            const uint8_t* arl = arow + (XS_L - XS_H);
            al[0] = *(const uint32_t*)(arl + oA);
            al[1] = *(const uint32_t*)(arl + 2048 + oA);
            al[2] = *(const uint32_t*)(arl + oA + 16);
            al[3] = *(const uint32_t*)(arl + 2048 + oA + 16);
#pragma unroll
            for (int nf = 0; nf < 8; nf++) {
                const uint8_t* brow = sb + Y1H + (nf * 8 + rsub) * 256;
                uint32_t bh0 = *(const uint32_t*)(brow + oA);
                uint32_t bh1 = *(const uint32_t*)(brow + oA + 16);
                uint32_t bl0 = *(const uint32_t*)(brow + 16384 + oA);
                uint32_t bl1 = *(const uint32_t*)(brow + 16384 + oA + 16);
                mma16816(s[nf], ah, bh0, bh1);
                mma16816(s[nf], ah, bl0, bl1);
                mma16816(s[nf], al, bh0, bh1);
                mma16816(s[nf], al, bl0, bl1);
            }
        }

        // ---- bias + online softmax (rows = lane quads; 2 shuffles per reduce) ----
        float mxa = -CUDART_INF_F, mxb = -CUDART_INF_F;
#pragma unroll
        for (int f = 0; f < 8; f++) {
            float2 y2v = *reinterpret_cast<const float2*>(&sh_y2[f * 8 + (lane & 3) * 2]);
            s[f][0] = fmaf(b2a, y2v.x, s[f][0]);
            s[f][1] = fmaf(b2a, y2v.y, s[f][1]);
            s[f][2] = fmaf(b2b, y2v.x, s[f][2]);
            s[f][3] = fmaf(b2b, y2v.y, s[f][3]);
            mxa = fmaxf(mxa, fmaxf(s[f][0], s[f][1]));
            mxb = fmaxf(mxb, fmaxf(s[f][2], s[f][3]));
        }
        mxa = fmaxf(mxa, __shfl_xor_sync(0xffffffffu, mxa, 1));
        mxa = fmaxf(mxa, __shfl_xor_sync(0xffffffffu, mxa, 2));
        mxb = fmaxf(mxb, __shfl_xor_sync(0xffffffffu, mxb, 1));
        mxb = fmaxf(mxb, __shfl_xor_sync(0xffffffffu, mxb, 2));
        float mna = fmaxf(m_a, mxa), mnb = fmaxf(m_b, mxb);
        float ala = fexp2(m_a - mna), alb = fexp2(m_b - mnb);
        m_a = mna; m_b = mnb;

        float suma = 0.0f, sumb = 0.0f;
        uint32_t ph[16], pl[16];
#pragma unroll
        for (int f = 0; f < 8; f++) {
            float p0 = fexp2(s[f][0] - mna), p1 = fexp2(s[f][1] - mna);
            float p2 = fexp2(s[f][2] - mnb), p3 = fexp2(s[f][3] - mnb);
            suma += p0 + p1; sumb += p2 + p3;
            split2(p0, p1, ph[2 * f], pl[2 * f]);
            split2(p2, p3, ph[2 * f + 1], pl[2 * f + 1]);
        }
        suma += __shfl_xor_sync(0xffffffffu, suma, 1);
        suma += __shfl_xor_sync(0xffffffffu, suma, 2);
        sumb += __shfl_xor_sync(0xffffffffu, sumb, 1);
        sumb += __shfl_xor_sync(0xffffffffu, sumb, 2);
        l_a = l_a * ala + suma;
        l_b = l_b * alb + sumb;
#pragma unroll
        for (int nf = 0; nf < 16; nf++) {
            o[nf][0] *= ala; o[nf][1] *= ala; o[nf][2] *= alb; o[nf][3] *= alb;
        }

        // ---- GEMM2: O[16][128] += P @ Y^T, 3-term split, K=64 ----
#pragma unroll
        for (int kc2 = 0; kc2 < 4; kc2++) {
            uint32_t ah[4] = { ph[4 * kc2], ph[4 * kc2 + 1], ph[4 * kc2 + 2], ph[4 * kc2 + 3] };
            uint32_t al_[4] = { pl[4 * kc2], pl[4 * kc2 + 1], pl[4 * kc2 + 2], pl[4 * kc2 + 3] };
            uint32_t k0 = (uint32_t)kc2 * 32 + lb4;
            uint32_t ob0 = k0 ^ swB, ob1 = (k0 + 16) ^ swB;
#pragma unroll
            for (int nf2 = 0; nf2 < 16; nf2++) {
                const uint8_t* brow = sb + YTH + (nf2 * 8 + rsub) * 128;
                uint32_t bh0 = *(const uint32_t*)(brow + ob0);
                uint32_t bh1 = *(const uint32_t*)(brow + ob1);
                uint32_t bl0 = *(const uint32_t*)(brow + 16384 + ob0);
                uint32_t bl1 = *(const uint32_t*)(brow + 16384 + ob1);
                mma16816(o[nf2], ah, bh0, bh1);
                mma16816(o[nf2], ah, bl0, bl1);
                mma16816(o[nf2], al_, bh0, bh1);
            }
        }
    }

    // ---- write split partials ----
    {
        int ga = r0 + rw + rsub;
        int gbrow = ga + 8;
        if ((lane & 3) == 0) {
            g_pm[q * NROWS + ga] = m_a;  g_pl[q * NROWS + ga] = l_a;
            g_pm[q * NROWS + gbrow] = m_b; g_pl[q * NROWS + gbrow] = l_b;
        }
        float* da = g_pO + ((size_t)(q * NROWS + ga)) * DDIM + (lane & 3) * 2;
        float* db = g_pO + ((size_t)(q * NROWS + gbrow)) * DDIM + (lane & 3) * 2;
#pragma unroll
        for (int nf = 0; nf < 16; nf++) {
            *reinterpret_cast<float2*>(da + nf * 8) = make_float2(o[nf][0], o[nf][1]);
            *reinterpret_cast<float2*>(db + nf * 8) = make_float2(o[nf][2], o[nf][3]);
        }
    }
}

// ---------------- merge splits + epilogue ----------------
__global__ void gmm_merge_kernel(const float* __restrict__ X, const float* __restrict__ T,
                                 float* __restrict__ out) {
    int row = blockIdx.x * 2 + (threadIdx.x >> 7);
    int d = threadIdx.x & 127;
    float tv = T[row];
    float lm = -0.25f * tv * tv * (BETA_MAX - BETA_MIN) - 0.5f * tv * BETA_MIN;
    float var = fmaxf(1.0f - expf(2.0f * lm), 1e-12f);
    float iv = 1.0f / var;
    float M = -CUDART_INF_F;
#pragma unroll
    for (int s = 0; s < SPLITK; s++) M = fmaxf(M, g_pm[s * NROWS + row]);
    float L = 0.0f, O = 0.0f;
#pragma unroll
    for (int s = 0; s < SPLITK; s++) {
        float w = fexp2(g_pm[s * NROWS + row] - M);
        L += g_pl[s * NROWS + row] * w;
        O += g_pO[((size_t)(s * NROWS + row)) * DDIM + d] * w;
    }
    out[(size_t)row * DDIM + d] = (O / L - X[(size_t)row * DDIM + d]) * iv;
}

// ---------------------------------------------------------------------------
extern "C" void kernel_launch(void* const* d_in, const int* in_sizes, int n_in,
                              void* d_out, int out_size) {
    (void)n_in; (void)out_size;
    const float* x = (const float*)d_in[0];
    const float* t = (const float*)d_in[1];
    const float* y = (const float*)d_in[2];
    float* out = (float*)d_out;
    int M = in_sizes[2] / DDIM;

    cudaFuncSetAttribute(gmm_main_kernel,
                         cudaFuncAttributeMaxDynamicSharedMemorySize, SMEM_BYTES);

    gmm_y2_kernel<<<(M + 7) / 8, dim3(32, 8)>>>(y, M);
    gmm_prep_kernel<<<TILES_ALL, 256>>>(y);
    gmm_main_kernel<<<(NROWS / BM) * SPLITK, 256, SMEM_BYTES>>>(x, t);
    gmm_merge_kernel<<<NROWS / 2, 256>>>(x, t, out);
}

// round 9
// speedup vs baseline: 7.0762x; 1.1510x over previous
#include <cuda_runtime.h>
#include <cuda_bf16.h>
#include <math_constants.h>
#include <cstdint>

#define BETA_MIN 0.1f
#define BETA_MAX 20.0f
#define LOG2E 1.4426950408889634f
#define DDIM 128
#define NROWS 4096
#define MKEYS 16384
#define SPLITK 4
#define BM 128
#define BN 64
#define NT 64            // key tiles per CTA (MKEYS/SPLITK/BN)
#define TILES_ALL 256

// smem layout: A tiles + 2 pipeline buffers
#define XS_H 0
#define XS_L 32768
#define BUF0 65536
#define BUFSTRIDE 66048        // 64KB blobs + 256B y2, 1KB-aligned
#define B_Y1H 0
#define B_Y1L 16384
#define B_YTH 32768
#define B_YTL 49152
#define B_Y2  65536
#define SMEM_BYTES (BUF0 + 2 * BUFSTRIDE)   // 197632

__device__ float g_y2[MKEYS];
__device__ uint4 g_y1h[TILES_ALL * 1024];   // Y tile [key][d], bf16 hi, XOR-swizzled
__device__ uint4 g_y1l[TILES_ALL * 1024];   // lo
__device__ uint4 g_yth[TILES_ALL * 1024];   // Y^T tile [d][key], bf16 hi, XOR-swizzled
__device__ uint4 g_ytl[TILES_ALL * 1024];   // lo
__device__ float g_pO[(size_t)SPLITK * NROWS * DDIM];
__device__ float g_pm[SPLITK * NROWS];
__device__ float g_pl[SPLITK * NROWS];

// ---------------- helpers ----------------
__device__ __forceinline__ uint32_t smem_u32(const void* p) {
    uint32_t a;
    asm("{ .reg .u64 t; cvta.to.shared.u64 t, %1; cvt.u32.u64 %0, t; }" : "=r"(a) : "l"(p));
    return a;
}
// fast 2^v for v <= 0 (clamped at -30), FFMA/ALU pipes only
__device__ __forceinline__ float fexp2(float v) {
    v = fmaxf(v, -30.0f);
    float r = v + 12582912.0f;
    int   n = __float_as_int(r) - 0x4B400000;
    float f = v - (r - 12582912.0f);
    float p = 1.3333558146e-3f;
    p = fmaf(p, f, 9.6181291918e-3f);
    p = fmaf(p, f, 5.5504108664e-2f);
    p = fmaf(p, f, 2.4022650696e-1f);
    p = fmaf(p, f, 6.9314718056e-1f);
    p = fmaf(p, f, 1.0f);
    return __int_as_float(__float_as_int(p) + (n << 23));
}
// split (a,b) -> bf16x2 hi (low half = a) + bf16x2 lo residual
__device__ __forceinline__ void split2(float a, float b, uint32_t& h, uint32_t& l) {
    uint32_t hp, lp;
    asm("cvt.rn.bf16x2.f32 %0, %1, %2;" : "=r"(hp) : "f"(b), "f"(a));
    float ra = a - __int_as_float(hp << 16);
    float rb = b - __int_as_float(hp & 0xFFFF0000u);
    asm("cvt.rn.bf16x2.f32 %0, %1, %2;" : "=r"(lp) : "f"(rb), "f"(ra));
    h = hp; l = lp;
}
__device__ __forceinline__ void mma16816(float* c, const uint32_t* a, uint32_t b0, uint32_t b1) {
    asm volatile("mma.sync.aligned.m16n8k16.row.col.f32.bf16.bf16.f32 "
        "{%0,%1,%2,%3}, {%4,%5,%6,%7}, {%8,%9}, {%0,%1,%2,%3};"
        : "+f"(c[0]), "+f"(c[1]), "+f"(c[2]), "+f"(c[3])
        : "r"(a[0]), "r"(a[1]), "r"(a[2]), "r"(a[3]), "r"(b0), "r"(b1));
}
__device__ __forceinline__ void cpa16(uint32_t s, const void* g) {
    asm volatile("cp.async.cg.shared.global [%0], [%1], 16;" :: "r"(s), "l"(g));
}
#define CP_COMMIT() asm volatile("cp.async.commit_group;" ::: "memory")
#define CP_WAIT1()  asm volatile("cp.async.wait_group 1;" ::: "memory")
#define CP_WAIT0()  asm volatile("cp.async.wait_group 0;" ::: "memory")

__device__ __forceinline__ void prefetch_tile(uint32_t bufb, int tg, int tid) {
    const uint4* s1 = g_y1h + tg * 1024;
    const uint4* s2 = g_y1l + tg * 1024;
    const uint4* s3 = g_yth + tg * 1024;
    const uint4* s4 = g_ytl + tg * 1024;
#pragma unroll
    for (int i = 0; i < 4; i++) {
        int idx = tid + 256 * i;
        cpa16(bufb + B_Y1H + idx * 16, s1 + idx);
        cpa16(bufb + B_Y1L + idx * 16, s2 + idx);
        cpa16(bufb + B_YTH + idx * 16, s3 + idx);
        cpa16(bufb + B_YTL + idx * 16, s4 + idx);
    }
    if (tid < 16) cpa16(bufb + B_Y2 + tid * 16, ((const uint4*)(g_y2 + tg * 64)) + tid);
}

// ---------------- precompute: y2 ----------------
__global__ void gmm_y2_kernel(const float* __restrict__ Y, int M) {
    int row = blockIdx.x * 8 + threadIdx.y;
    if (row >= M) return;
    int l = threadIdx.x;
    float4 v = *reinterpret_cast<const float4*>(Y + (size_t)row * DDIM + l * 4);
    float s = v.x * v.x + v.y * v.y + v.z * v.z + v.w * v.w;
#pragma unroll
    for (int off = 16; off > 0; off >>= 1) s += __shfl_xor_sync(0xffffffffu, s, off);
    if (l == 0) g_y2[row] = s;
}

// ---------------- precompute: split + swizzled tile blobs ----------------
__global__ void gmm_prep_kernel(const float* __restrict__ Y) {
    int tile = blockIdx.x, t = threadIdx.x, c0 = tile * BN;
    {
        int key = t >> 2, dq = (t & 3) * 32;
        const float* src = Y + (size_t)(c0 + key) * DDIM;
#pragma unroll
        for (int i = 0; i < 4; i++) {
            int d = dq + 8 * i;
            float4 v0 = *reinterpret_cast<const float4*>(src + d);
            float4 v1 = *reinterpret_cast<const float4*>(src + d + 4);
            uint32_t hh[4], ll[4];
            split2(v0.x, v0.y, hh[0], ll[0]); split2(v0.z, v0.w, hh[1], ll[1]);
            split2(v1.x, v1.y, hh[2], ll[2]); split2(v1.z, v1.w, hh[3], ll[3]);
            uint32_t off = (uint32_t)key * 256 + ((uint32_t)(d * 2) ^ ((key & 7) * 32));
            g_y1h[tile * 1024 + off / 16] = make_uint4(hh[0], hh[1], hh[2], hh[3]);
            g_y1l[tile * 1024 + off / 16] = make_uint4(ll[0], ll[1], ll[2], ll[3]);
        }
    }
    {
        int dim = t >> 1, kh = (t & 1) * 32;
#pragma unroll
        for (int i = 0; i < 4; i++) {
            int k0 = kh + 8 * i;
            float pv[8];
#pragma unroll
            for (int u = 0; u < 8; u++) pv[u] = Y[(size_t)(c0 + k0 + u) * DDIM + dim];
            uint32_t hh[4], ll[4];
            split2(pv[0], pv[1], hh[0], ll[0]); split2(pv[2], pv[3], hh[1], ll[1]);
            split2(pv[4], pv[5], hh[2], ll[2]); split2(pv[6], pv[7], hh[3], ll[3]);
            uint32_t off = (uint32_t)dim * 128 + ((uint32_t)(k0 * 2) ^ ((dim & 7) * 16));
            g_yth[tile * 1024 + off / 16] = make_uint4(hh[0], hh[1], hh[2], hh[3]);
            g_ytl[tile * 1024 + off / 16] = make_uint4(ll[0], ll[1], ll[2], ll[3]);
        }
    }
}

// ---------------- main fused kernel ----------------
__global__ __launch_bounds__(256, 1)
void gmm_main_kernel(const float* __restrict__ X, const float* __restrict__ T) {
    extern __shared__ uint8_t sb[];
    __shared__ float sh_a2[BM], sh_b2[BM];

    const int tid = threadIdx.x, lane = tid & 31, wid = tid >> 5;
    const int rb = blockIdx.x >> 2, q = blockIdx.x & 3;
    const int r0 = rb * BM;
    const int rw = wid * 16;
    const int rsub = lane >> 2;
    const uint32_t lb4 = (uint32_t)(lane & 3) * 4;
    const uint32_t swA = (uint32_t)rsub * 32;
    const uint32_t swB = (uint32_t)rsub * 16;
    const uint32_t sb0 = smem_u32(sb);

    if (tid < BM) {
        float tv = T[r0 + tid];
        float lm = -0.25f * tv * tv * (BETA_MAX - BETA_MIN) - 0.5f * tv * BETA_MIN;
        float mean = expf(lm);
        float var = fmaxf(1.0f - expf(2.0f * lm), 1e-12f);
        float iv = 1.0f / var;
        sh_a2[tid] = mean * iv * LOG2E;
        sh_b2[tid] = -0.5f * mean * mean * iv * LOG2E;
    }
    // kick off prefetch of tile 0 ASAP
    prefetch_tile(sb0 + BUF0, q * NT, tid);
    CP_COMMIT();
    __syncthreads();

    // Build A = a2_r * x_r in smem, bf16 split, swizzled [128 rows][128 d]
    {
        int row = tid >> 1, half = tid & 1;
        float a2 = sh_a2[row];
        const float* src = X + (size_t)(r0 + row) * DDIM + half * 64;
#pragma unroll
        for (int i = 0; i < 8; i++) {
            int d = half * 64 + 8 * i;
            float4 v0 = *reinterpret_cast<const float4*>(src + 8 * i);
            float4 v1 = *reinterpret_cast<const float4*>(src + 8 * i + 4);
            uint32_t hh[4], ll[4];
            split2(a2 * v0.x, a2 * v0.y, hh[0], ll[0]);
            split2(a2 * v0.z, a2 * v0.w, hh[1], ll[1]);
            split2(a2 * v1.x, a2 * v1.y, hh[2], ll[2]);
            split2(a2 * v1.z, a2 * v1.w, hh[3], ll[3]);
            uint32_t off = (uint32_t)row * 256 + ((uint32_t)(d * 2) ^ ((row & 7) * 32));
            *reinterpret_cast<uint4*>(sb + XS_H + off) = make_uint4(hh[0], hh[1], hh[2], hh[3]);
            *reinterpret_cast<uint4*>(sb + XS_L + off) = make_uint4(ll[0], ll[1], ll[2], ll[3]);
        }
    }

    const float b2a = sh_b2[rw + rsub];
    const float b2b = sh_b2[rw + rsub + 8];

    float o[16][4];
#pragma unroll
    for (int i = 0; i < 16; i++)
#pragma unroll
        for (int j = 0; j < 4; j++) o[i][j] = 0.0f;
    float m_a = -CUDART_INF_F, m_b = -CUDART_INF_F, l_a = 0.0f, l_b = 0.0f;

    for (int kt = 0; kt < NT; kt++) {
        const int cur = kt & 1;
        const uint8_t* buf = sb + BUF0 + cur * BUFSTRIDE;

        // prefetch next tile into the other buffer (freed by end-of-iter barrier of kt-1)
        if (kt + 1 < NT) {
            prefetch_tile(sb0 + BUF0 + (1 - cur) * BUFSTRIDE, q * NT + kt + 1, tid);
            CP_COMMIT();
            CP_WAIT1();
        } else {
            CP_WAIT0();
        }
        __syncthreads();   // buf[cur] visible to all threads

        // ---- GEMM1: S[16][64] per warp, 3-term bf16 split, K=128 ----
        float s[8][4];
#pragma unroll
        for (int i = 0; i < 8; i++)
#pragma unroll
            for (int j = 0; j < 4; j++) s[i][j] = 0.0f;

#pragma unroll 2
        for (int kc = 0; kc < 8; kc++) {
            uint32_t oA = ((uint32_t)kc * 32 + lb4) ^ swA;
            const uint8_t* arow = sb + XS_H + (rw + rsub) * 256;
            uint32_t ah[4], al[4];
            ah[0] = *(const uint32_t*)(arow + oA);
            ah[1] = *(const uint32_t*)(arow + 2048 + oA);
            ah[2] = *(const uint32_t*)(arow + oA + 16);
            ah[3] = *(const uint32_t*)(arow + 2048 + oA + 16);
            const uint8_t* arl = arow + (XS_L - XS_H);
            al[0] = *(const uint32_t*)(arl + oA);
            al[1] = *(const uint32_t*)(arl + 2048 + oA);
            al[2] = *(const uint32_t*)(arl + oA + 16);
            al[3] = *(const uint32_t*)(arl + 2048 + oA + 16);
#pragma unroll
            for (int nf = 0; nf < 8; nf++) {
                const uint8_t* brow = buf + B_Y1H + (nf * 8 + rsub) * 256;
                uint32_t bh0 = *(const uint32_t*)(brow + oA);
                uint32_t bh1 = *(const uint32_t*)(brow + oA + 16);
                uint32_t bl0 = *(const uint32_t*)(brow + (B_Y1L - B_Y1H) + oA);
                uint32_t bl1 = *(const uint32_t*)(brow + (B_Y1L - B_Y1H) + oA + 16);
                mma16816(s[nf], ah, bh0, bh1);
                mma16816(s[nf], ah, bl0, bl1);
                mma16816(s[nf], al, bh0, bh1);
            }
        }

        // ---- bias + online softmax ----
        const float* y2p = (const float*)(buf + B_Y2);
        float mxa = -CUDART_INF_F, mxb = -CUDART_INF_F;
#pragma unroll
        for (int f = 0; f < 8; f++) {
            float2 y2v = *reinterpret_cast<const float2*>(y2p + f * 8 + (lane & 3) * 2);
            s[f][0] = fmaf(b2a, y2v.x, s[f][0]);
            s[f][1] = fmaf(b2a, y2v.y, s[f][1]);
            s[f][2] = fmaf(b2b, y2v.x, s[f][2]);
            s[f][3] = fmaf(b2b, y2v.y, s[f][3]);
            mxa = fmaxf(mxa, fmaxf(s[f][0], s[f][1]));
            mxb = fmaxf(mxb, fmaxf(s[f][2], s[f][3]));
        }
        mxa = fmaxf(mxa, __shfl_xor_sync(0xffffffffu, mxa, 1));
        mxa = fmaxf(mxa, __shfl_xor_sync(0xffffffffu, mxa, 2));
        mxb = fmaxf(mxb, __shfl_xor_sync(0xffffffffu, mxb, 1));
        mxb = fmaxf(mxb, __shfl_xor_sync(0xffffffffu, mxb, 2));
        float mna = fmaxf(m_a, mxa), mnb = fmaxf(m_b, mxb);
        float ala = fexp2(m_a - mna), alb = fexp2(m_b - mnb);
        m_a = mna; m_b = mnb;

        float suma = 0.0f, sumb = 0.0f;
        uint32_t ph[16], pl[16];
#pragma unroll
        for (int f = 0; f < 8; f++) {
            float p0 = fexp2(s[f][0] - mna), p1 = fexp2(s[f][1] - mna);
            float p2 = fexp2(s[f][2] - mnb), p3 = fexp2(s[f][3] - mnb);
            suma += p0 + p1; sumb += p2 + p3;
            split2(p0, p1, ph[2 * f], pl[2 * f]);
            split2(p2, p3, ph[2 * f + 1], pl[2 * f + 1]);
        }
        suma += __shfl_xor_sync(0xffffffffu, suma, 1);
        suma += __shfl_xor_sync(0xffffffffu, suma, 2);
        sumb += __shfl_xor_sync(0xffffffffu, sumb, 1);
        sumb += __shfl_xor_sync(0xffffffffu, sumb, 2);
        l_a = l_a * ala + suma;
        l_b = l_b * alb + sumb;
#pragma unroll
        for (int nf = 0; nf < 16; nf++) {
            o[nf][0] *= ala; o[nf][1] *= ala; o[nf][2] *= alb; o[nf][3] *= alb;
        }

        // ---- GEMM2: O[16][128] += P @ Y^T, 3-term split, K=64 ----
#pragma unroll
        for (int kc2 = 0; kc2 < 4; kc2++) {
            uint32_t ah[4] = { ph[4 * kc2], ph[4 * kc2 + 1], ph[4 * kc2 + 2], ph[4 * kc2 + 3] };
            uint32_t al_[4] = { pl[4 * kc2], pl[4 * kc2 + 1], pl[4 * kc2 + 2], pl[4 * kc2 + 3] };
            uint32_t k0 = (uint32_t)kc2 * 32 + lb4;
            uint32_t ob0 = k0 ^ swB, ob1 = (k0 + 16) ^ swB;
#pragma unroll
            for (int nf2 = 0; nf2 < 16; nf2++) {
                const uint8_t* brow = buf + B_YTH + (nf2 * 8 + rsub) * 128;
                uint32_t bh0 = *(const uint32_t*)(brow + ob0);
                uint32_t bh1 = *(const uint32_t*)(brow + ob1);
                uint32_t bl0 = *(const uint32_t*)(brow + (B_YTL - B_YTH) + ob0);
                uint32_t bl1 = *(const uint32_t*)(brow + (B_YTL - B_YTH) + ob1);
                mma16816(o[nf2], ah, bh0, bh1);
                mma16816(o[nf2], ah, bl0, bl1);
                mma16816(o[nf2], al_, bh0, bh1);
            }
        }
        __syncthreads();   // all warps done with buf[cur] before next prefetch overwrites it
    }

    // ---- write split partials ----
    {
        int ga = r0 + rw + rsub;
        int gbrow = ga + 8;
        if ((lane & 3) == 0) {
            g_pm[q * NROWS + ga] = m_a;  g_pl[q * NROWS + ga] = l_a;
            g_pm[q * NROWS + gbrow] = m_b; g_pl[q * NROWS + gbrow] = l_b;
        }
        float* da = g_pO + ((size_t)(q * NROWS + ga)) * DDIM + (lane & 3) * 2;
        float* db = g_pO + ((size_t)(q * NROWS + gbrow)) * DDIM + (lane & 3) * 2;
#pragma unroll
        for (int nf = 0; nf < 16; nf++) {
            *reinterpret_cast<float2*>(da + nf * 8) = make_float2(o[nf][0], o[nf][1]);
            *reinterpret_cast<float2*>(db + nf * 8) = make_float2(o[nf][2], o[nf][3]);
        }
    }
}

// ---------------- merge splits + epilogue ----------------
__global__ void gmm_merge_kernel(const float* __restrict__ X, const float* __restrict__ T,
                                 float* __restrict__ out) {
    int row = blockIdx.x * 2 + (threadIdx.x >> 7);
    int d = threadIdx.x & 127;
    float tv = T[row];
    float lm = -0.25f * tv * tv * (BETA_MAX - BETA_MIN) - 0.5f * tv * BETA_MIN;
    float var = fmaxf(1.0f - expf(2.0f * lm), 1e-12f);
    float iv = 1.0f / var;
    float M = -CUDART_INF_F;
#pragma unroll
    for (int s = 0; s < SPLITK; s++) M = fmaxf(M, g_pm[s * NROWS + row]);
    float L = 0.0f, O = 0.0f;
#pragma unroll
    for (int s = 0; s < SPLITK; s++) {
        float w = fexp2(g_pm[s * NROWS + row] - M);
        L += g_pl[s * NROWS + row] * w;
        O += g_pO[((size_t)(s * NROWS + row)) * DDIM + d] * w;
    }
    out[(size_t)row * DDIM + d] = (O / L - X[(size_t)row * DDIM + d]) * iv;
}

// ---------------------------------------------------------------------------
extern "C" void kernel_launch(void* const* d_in, const int* in_sizes, int n_in,
                              void* d_out, int out_size) {
    (void)n_in; (void)out_size;
    const float* x = (const float*)d_in[0];
    const float* t = (const float*)d_in[1];
    const float* y = (const float*)d_in[2];
    float* out = (float*)d_out;
    int M = in_sizes[2] / DDIM;

    cudaFuncSetAttribute(gmm_main_kernel,
                         cudaFuncAttributeMaxDynamicSharedMemorySize, SMEM_BYTES);

    gmm_y2_kernel<<<(M + 7) / 8, dim3(32, 8)>>>(y, M);
    gmm_prep_kernel<<<TILES_ALL, 256>>>(y);
    gmm_main_kernel<<<(NROWS / BM) * SPLITK, 256, SMEM_BYTES>>>(x, t);
    gmm_merge_kernel<<<NROWS / 2, 256>>>(x, t, out);
}

// round 10
// speedup vs baseline: 7.9757x; 1.1271x over previous
#include <cuda_runtime.h>
#include <cuda_bf16.h>
#include <math_constants.h>
#include <cstdint>

#define BETA_MIN 0.1f
#define BETA_MAX 20.0f
#define LOG2E 1.4426950408889634f
#define DDIM 128
#define NROWS 4096
#define MKEYS 16384
#define SPLITK 4
#define BM 128
#define BN 64
#define NT 64            // key tiles per CTA (MKEYS/SPLITK/BN)
#define TILES_ALL 256

// smem layout
#define XS   0                 // A tile fused hi/lo: 128 rows * 512B = 64KB
#define BUF0 65536
#define BUFSTRIDE 66048        // 64KB blobs + 256B y2, 1KB aligned
#define B_G1 0                 // GEMM1 fused blob, 32KB
#define B_G2 32768             // GEMM2 fused blob, 32KB
#define B_Y2 65536
#define SMEM_BYTES (BUF0 + 2 * BUFSTRIDE)   // 197632

__device__ float g_y2[MKEYS];
__device__ uint4 g_yc1[TILES_ALL * 2048];   // fused GEMM1 B blobs (hi+lo interleaved)
__device__ uint4 g_yc2[TILES_ALL * 2048];   // fused GEMM2 B blobs
__device__ float g_pO[(size_t)SPLITK * NROWS * DDIM];
__device__ float g_pm[SPLITK * NROWS];
__device__ float g_pl[SPLITK * NROWS];

// ---------------- helpers ----------------
__device__ __forceinline__ uint32_t smem_u32(const void* p) {
    uint32_t a;
    asm("{ .reg .u64 t; cvta.to.shared.u64 t, %1; cvt.u32.u64 %0, t; }" : "=r"(a) : "l"(p));
    return a;
}
// fast 2^v for v <= 0 (clamped at -30), FFMA/ALU pipes only
__device__ __forceinline__ float fexp2(float v) {
    v = fmaxf(v, -30.0f);
    float r = v + 12582912.0f;
    int   n = __float_as_int(r) - 0x4B400000;
    float f = v - (r - 12582912.0f);
    float p = 1.3333558146e-3f;
    p = fmaf(p, f, 9.6181291918e-3f);
    p = fmaf(p, f, 5.5504108664e-2f);
    p = fmaf(p, f, 2.4022650696e-1f);
    p = fmaf(p, f, 6.9314718056e-1f);
    p = fmaf(p, f, 1.0f);
    return __int_as_float(__float_as_int(p) + (n << 23));
}
// split (a,b) -> bf16x2 hi (low half = a) + bf16x2 lo residual
__device__ __forceinline__ void split2(float a, float b, uint32_t& h, uint32_t& l) {
    uint32_t hp, lp;
    asm("cvt.rn.bf16x2.f32 %0, %1, %2;" : "=r"(hp) : "f"(b), "f"(a));
    float ra = a - __int_as_float(hp << 16);
    float rb = b - __int_as_float(hp & 0xFFFF0000u);
    asm("cvt.rn.bf16x2.f32 %0, %1, %2;" : "=r"(lp) : "f"(rb), "f"(ra));
    h = hp; l = lp;
}
__device__ __forceinline__ void mma16816(float* c, const uint32_t* a, uint32_t b0, uint32_t b1) {
    asm volatile("mma.sync.aligned.m16n8k16.row.col.f32.bf16.bf16.f32 "
        "{%0,%1,%2,%3}, {%4,%5,%6,%7}, {%8,%9}, {%0,%1,%2,%3};"
        : "+f"(c[0]), "+f"(c[1]), "+f"(c[2]), "+f"(c[3])
        : "r"(a[0]), "r"(a[1]), "r"(a[2]), "r"(a[3]), "r"(b0), "r"(b1));
}
__device__ __forceinline__ void cpa16(uint32_t s, const void* g) {
    asm volatile("cp.async.cg.shared.global [%0], [%1], 16;" :: "r"(s), "l"(g));
}
#define CP_COMMIT() asm volatile("cp.async.commit_group;" ::: "memory")
#define CP_WAIT1()  asm volatile("cp.async.wait_group 1;" ::: "memory")
#define CP_WAIT0()  asm volatile("cp.async.wait_group 0;" ::: "memory")

__device__ __forceinline__ void prefetch_tile(uint32_t bufb, int tg, int tid) {
    const uint4* s1 = g_yc1 + tg * 2048;
    const uint4* s2 = g_yc2 + tg * 2048;
#pragma unroll
    for (int i = 0; i < 8; i++) {
        int idx = tid + 256 * i;
        cpa16(bufb + B_G1 + idx * 16, s1 + idx);
        cpa16(bufb + B_G2 + idx * 16, s2 + idx);
    }
    if (tid < 16) cpa16(bufb + B_Y2 + tid * 16, ((const uint4*)(g_y2 + tg * 64)) + tid);
}

// ---------------- precompute: y2 ----------------
__global__ void gmm_y2_kernel(const float* __restrict__ Y, int M) {
    int row = blockIdx.x * 8 + threadIdx.y;
    if (row >= M) return;
    int l = threadIdx.x;
    float4 v = *reinterpret_cast<const float4*>(Y + (size_t)row * DDIM + l * 4);
    float s = v.x * v.x + v.y * v.y + v.z * v.z + v.w * v.w;
#pragma unroll
    for (int off = 16; off > 0; off >>= 1) s += __shfl_xor_sync(0xffffffffu, s, off);
    if (l == 0) g_y2[row] = s;
}

// ---------------- precompute: fused split blobs (smem-staged) ----------------
__global__ void gmm_prep_kernel(const float* __restrict__ Y) {
    __shared__ float ys[BN * DDIM];       // 32KB tile of Y
    const int tile = blockIdx.x, tid = threadIdx.x;
    const float* src = Y + (size_t)tile * BN * DDIM;
#pragma unroll
    for (int i = 0; i < 8; i++) {
        int idx = tid + 256 * i;
        *reinterpret_cast<float4*>(ys + idx * 4) =
            *reinterpret_cast<const float4*>(src + idx * 4);
    }
    __syncthreads();

    // GEMM1 blob: slot s -> (kc = s>>8, nf = (s>>5)&7, rs = (s>>2)&7, q = s&3)
    // content: Y[n = nf*8+rs][kb..kb+1], [kb+8..kb+9], kb = kc*16 + q*2; words {h0,h1,l0,l1}
#pragma unroll
    for (int j = 0; j < 8; j++) {
        int s = tid + 256 * j;
        int kc = s >> 8, nf = (s >> 5) & 7, rs = (s >> 2) & 7, q = s & 3;
        int n = nf * 8 + rs, kb = kc * 16 + q * 2;
        const float* row = ys + n * DDIM;
        uint32_t h0, l0, h1, l1;
        split2(row[kb], row[kb + 1], h0, l0);
        split2(row[kb + 8], row[kb + 9], h1, l1);
        g_yc1[tile * 2048 + s] = make_uint4(h0, h1, l0, l1);
    }
    // GEMM2 blob: slot s -> (kc2 = s>>9, nf2 = (s>>5)&15, rs = (s>>2)&7, q = s&3)
    // content: Y^T[k][d]: d = nf2*8+rs, k = kc2*16 + q*2 (+1, +8, +9)
#pragma unroll
    for (int j = 0; j < 8; j++) {
        int s = tid + 256 * j;
        int kc2 = s >> 9, nf2 = (s >> 5) & 15, rs = (s >> 2) & 7, q = s & 3;
        int d = nf2 * 8 + rs, k = kc2 * 16 + q * 2;
        uint32_t h0, l0, h1, l1;
        split2(ys[k * DDIM + d], ys[(k + 1) * DDIM + d], h0, l0);
        split2(ys[(k + 8) * DDIM + d], ys[(k + 9) * DDIM + d], h1, l1);
        g_yc2[tile * 2048 + s] = make_uint4(h0, h1, l0, l1);
    }
}

// ---------------- main fused kernel ----------------
__global__ __launch_bounds__(256, 1)
void gmm_main_kernel(const float* __restrict__ X, const float* __restrict__ T) {
    extern __shared__ uint8_t sb[];
    __shared__ float sh_a2[BM], sh_b2[BM];

    const int tid = threadIdx.x, lane = tid & 31, wid = tid >> 5;
    const int rb = blockIdx.x >> 2, q = blockIdx.x & 3;
    const int r0 = rb * BM;
    const int rw = wid * 16;
    const int rsub = lane >> 2;
    const int lq = lane & 3;
    const uint32_t sb0 = smem_u32(sb);

    if (tid < BM) {
        float tv = T[r0 + tid];
        float lm = -0.25f * tv * tv * (BETA_MAX - BETA_MIN) - 0.5f * tv * BETA_MIN;
        float mean = expf(lm);
        float var = fmaxf(1.0f - expf(2.0f * lm), 1e-12f);
        float iv = 1.0f / var;
        sh_a2[tid] = mean * iv * LOG2E;
        sh_b2[tid] = -0.5f * mean * mean * iv * LOG2E;
    }
    // kick off prefetch of tile 0 ASAP
    prefetch_tile(sb0 + BUF0, q * NT, tid);
    CP_COMMIT();
    __syncthreads();

    // Build A = a2_r * x_r, fused hi/lo layout:
    // addr(row, kc, q) = row*512 + (kc ^ (row&7))*64 + q*16; words {h(k0,k1), h(k8,k9), l, l}
    {
        int row = tid >> 1, half = tid & 1;
        float a2 = sh_a2[row];
        const float* src = X + (size_t)(r0 + row) * DDIM;
        uint8_t* abase = sb + XS + row * 512;
#pragma unroll
        for (int kc = half * 4; kc < half * 4 + 4; kc++) {
#pragma unroll
            for (int qq = 0; qq < 4; qq++) {
                int d = kc * 16 + qq * 2;
                float2 v0 = *reinterpret_cast<const float2*>(src + d);
                float2 v1 = *reinterpret_cast<const float2*>(src + d + 8);
                uint32_t h0, l0, h1, l1;
                split2(a2 * v0.x, a2 * v0.y, h0, l0);
                split2(a2 * v1.x, a2 * v1.y, h1, l1);
                *reinterpret_cast<uint4*>(abase + ((kc ^ (row & 7)) * 64 + qq * 16)) =
                    make_uint4(h0, h1, l0, l1);
            }
        }
    }

    const float b2a = sh_b2[rw + rsub];
    const float b2b = sh_b2[rw + rsub + 8];

    float o[16][4];
#pragma unroll
    for (int i = 0; i < 16; i++)
#pragma unroll
        for (int j = 0; j < 4; j++) o[i][j] = 0.0f;
    float m_a = -CUDART_INF_F, m_b = -CUDART_INF_F, l_a = 0.0f, l_b = 0.0f;

    for (int kt = 0; kt < NT; kt++) {
        const int cur = kt & 1;
        const uint8_t* buf = sb + BUF0 + cur * BUFSTRIDE;

        if (kt + 1 < NT) {
            prefetch_tile(sb0 + BUF0 + (1 - cur) * BUFSTRIDE, q * NT + kt + 1, tid);
            CP_COMMIT();
            CP_WAIT1();
        } else {
            CP_WAIT0();
        }
        __syncthreads();

        // ---- GEMM1: S[16][64] per warp, 3-term bf16 split, K=128 ----
        float s[8][4];
#pragma unroll
        for (int i = 0; i < 8; i++)
#pragma unroll
            for (int j = 0; j < 4; j++) s[i][j] = 0.0f;

        const uint8_t* arow1 = sb + XS + (rw + rsub) * 512;
        const uint8_t* arow2 = arow1 + 8 * 512;
#pragma unroll 2
        for (int kc = 0; kc < 8; kc++) {
            uint32_t oA = (uint32_t)((kc ^ rsub) * 64 + lq * 16);
            uint4 ua = *reinterpret_cast<const uint4*>(arow1 + oA);
            uint4 ub = *reinterpret_cast<const uint4*>(arow2 + oA);
            uint32_t ah[4] = { ua.x, ub.x, ua.y, ub.y };
            uint32_t al[4] = { ua.z, ub.z, ua.w, ub.w };
            const uint8_t* bbase = buf + B_G1 + kc * 4096 + lane * 16;
#pragma unroll
            for (int nf = 0; nf < 8; nf++) {
                uint4 bb = *reinterpret_cast<const uint4*>(bbase + nf * 512);
                mma16816(s[nf], ah, bb.x, bb.y);
                mma16816(s[nf], ah, bb.z, bb.w);
                mma16816(s[nf], al, bb.x, bb.y);
            }
        }

        // ---- bias + online softmax ----
        const float* y2p = (const float*)(buf + B_Y2);
        float mxa = -CUDART_INF_F, mxb = -CUDART_INF_F;
#pragma unroll
        for (int f = 0; f < 8; f++) {
            float2 y2v = *reinterpret_cast<const float2*>(y2p + f * 8 + lq * 2);
            s[f][0] = fmaf(b2a, y2v.x, s[f][0]);
            s[f][1] = fmaf(b2a, y2v.y, s[f][1]);
            s[f][2] = fmaf(b2b, y2v.x, s[f][2]);
            s[f][3] = fmaf(b2b, y2v.y, s[f][3]);
            mxa = fmaxf(mxa, fmaxf(s[f][0], s[f][1]));
            mxb = fmaxf(mxb, fmaxf(s[f][2], s[f][3]));
        }
        mxa = fmaxf(mxa, __shfl_xor_sync(0xffffffffu, mxa, 1));
        mxa = fmaxf(mxa, __shfl_xor_sync(0xffffffffu, mxa, 2));
        mxb = fmaxf(mxb, __shfl_xor_sync(0xffffffffu, mxb, 1));
        mxb = fmaxf(mxb, __shfl_xor_sync(0xffffffffu, mxb, 2));
        float mna = fmaxf(m_a, mxa), mnb = fmaxf(m_b, mxb);
        float ala = fexp2(m_a - mna), alb = fexp2(m_b - mnb);
        m_a = mna; m_b = mnb;

        float suma = 0.0f, sumb = 0.0f;
        uint32_t ph[16], pl[16];
#pragma unroll
        for (int f = 0; f < 8; f++) {
            float p0 = fexp2(s[f][0] - mna), p1 = fexp2(s[f][1] - mna);
            float p2 = fexp2(s[f][2] - mnb), p3 = fexp2(s[f][3] - mnb);
            suma += p0 + p1; sumb += p2 + p3;
            split2(p0, p1, ph[2 * f], pl[2 * f]);
            split2(p2, p3, ph[2 * f + 1], pl[2 * f + 1]);
        }
        suma += __shfl_xor_sync(0xffffffffu, suma, 1);
        suma += __shfl_xor_sync(0xffffffffu, suma, 2);
        sumb += __shfl_xor_sync(0xffffffffu, sumb, 1);
        sumb += __shfl_xor_sync(0xffffffffu, sumb, 2);
        l_a = l_a * ala + suma;
        l_b = l_b * alb + sumb;
#pragma unroll
        for (int nf = 0; nf < 16; nf++) {
            o[nf][0] *= ala; o[nf][1] *= ala; o[nf][2] *= alb; o[nf][3] *= alb;
        }

        // ---- GEMM2: O[16][128] += P @ Y^T, 3-term split, K=64 ----
#pragma unroll
        for (int kc2 = 0; kc2 < 4; kc2++) {
            uint32_t ah[4] = { ph[4 * kc2], ph[4 * kc2 + 1], ph[4 * kc2 + 2], ph[4 * kc2 + 3] };
            uint32_t al_[4] = { pl[4 * kc2], pl[4 * kc2 + 1], pl[4 * kc2 + 2], pl[4 * kc2 + 3] };
            const uint8_t* bbase = buf + B_G2 + kc2 * 8192 + lane * 16;
#pragma unroll
            for (int nf2 = 0; nf2 < 16; nf2++) {
                uint4 bb = *reinterpret_cast<const uint4*>(bbase + nf2 * 512);
                mma16816(o[nf2], ah, bb.x, bb.y);
                mma16816(o[nf2], ah, bb.z, bb.w);
                mma16816(o[nf2], al_, bb.x, bb.y);
            }
        }
        __syncthreads();   // all warps done with buf[cur] before next prefetch overwrites it
    }

    // ---- write split partials ----
    {
        int ga = r0 + rw + rsub;
        int gbrow = ga + 8;
        if (lq == 0) {
            g_pm[q * NROWS + ga] = m_a;  g_pl[q * NROWS + ga] = l_a;
            g_pm[q * NROWS + gbrow] = m_b; g_pl[q * NROWS + gbrow] = l_b;
        }
        float* da = g_pO + ((size_t)(q * NROWS + ga)) * DDIM + lq * 2;
        float* db = g_pO + ((size_t)(q * NROWS + gbrow)) * DDIM + lq * 2;
#pragma unroll
        for (int nf = 0; nf < 16; nf++) {
            *reinterpret_cast<float2*>(da + nf * 8) = make_float2(o[nf][0], o[nf][1]);
            *reinterpret_cast<float2*>(db + nf * 8) = make_float2(o[nf][2], o[nf][3]);
        }
    }
}

// ---------------- merge splits + epilogue ----------------
__global__ void gmm_merge_kernel(const float* __restrict__ X, const float* __restrict__ T,
                                 float* __restrict__ out) {
    int row = blockIdx.x * 2 + (threadIdx.x >> 7);
    int d = threadIdx.x & 127;
    float tv = T[row];
    float lm = -0.25f * tv * tv * (BETA_MAX - BETA_MIN) - 0.5f * tv * BETA_MIN;
    float var = fmaxf(1.0f - expf(2.0f * lm), 1e-12f);
    float iv = 1.0f / var;
    float M = -CUDART_INF_F;
#pragma unroll
    for (int s = 0; s < SPLITK; s++) M = fmaxf(M, g_pm[s * NROWS + row]);
    float L = 0.0f, O = 0.0f;
#pragma unroll
    for (int s = 0; s < SPLITK; s++) {
        float w = fexp2(g_pm[s * NROWS + row] - M);
        L += g_pl[s * NROWS + row] * w;
        O += g_pO[((size_t)(s * NROWS + row)) * DDIM + d] * w;
    }
    out[(size_t)row * DDIM + d] = (O / L - X[(size_t)row * DDIM + d]) * iv;
}

// ---------------------------------------------------------------------------
extern "C" void kernel_launch(void* const* d_in, const int* in_sizes, int n_in,
                              void* d_out, int out_size) {
    (void)n_in; (void)out_size;
    const float* x = (const float*)d_in[0];
    const float* t = (const float*)d_in[1];
    const float* y = (const float*)d_in[2];
    float* out = (float*)d_out;
    int M = in_sizes[2] / DDIM;

    cudaFuncSetAttribute(gmm_main_kernel,
                         cudaFuncAttributeMaxDynamicSharedMemorySize, SMEM_BYTES);

    gmm_y2_kernel<<<(M + 7) / 8, dim3(32, 8)>>>(y, M);
    gmm_prep_kernel<<<TILES_ALL, 256>>>(y);
    gmm_main_kernel<<<(NROWS / BM) * SPLITK, 256, SMEM_BYTES>>>(x, t);
    gmm_merge_kernel<<<NROWS / 2, 256>>>(x, t, out);
}